// round 9
// baseline (speedup 1.0000x reference)
#include <cuda_runtime.h>
#include <cuda_bf16.h>
#include <math.h>

#define Bq 4
#define Lq 6
#define Qq 900
#define Cq 256
#define Nq (Lq*Qq)            /* 5400 */
#define BM2 128
#define NT2 ((Nq+BM2-1)/BM2)  /* 43 */
#define TRI (NT2*(NT2+1)/2)   /* 946 */
#define BKB 64                /* K bytes per stage (fp8) */
#define ROWP 80               /* padded smem row bytes (16-aligned, conflict-free) */
#define NSTG 4
#define DUP_THR 0.8f
#define DSMEM_BYTES (2*NSTG*BM2*ROWP)   /* 81920 */

typedef unsigned long long ull;

// ---------------- scratch ----------------
__device__ unsigned char g_normF8[(size_t)Bq*Nq*Cq];   // fp8 e4m3 normalized rows
__device__ int           g_selList[Bq*Nq];
__device__ int           g_parent[Bq*Nq];
__device__ ull           g_best[Bq*Nq];
__device__ unsigned char g_sel[Bq*Nq];
__device__ float         g_score[Bq*Nq];
__device__ int           g_slotNode[Bq*Nq];
__device__ int           g_selCount[Bq];
__device__ int           g_seedCount[Bq];

// ---------------- ptx helpers ----------------
__device__ __forceinline__ void cp16(void* smp, const void* g){
    unsigned sa = (unsigned)__cvta_generic_to_shared(smp);
    asm volatile("cp.async.cg.shared.global [%0], [%1], 16;\n" :: "r"(sa), "l"(g));
}
__device__ __forceinline__ void cp_commit(){ asm volatile("cp.async.commit_group;\n"); }
template<int N> __device__ __forceinline__ void cp_wait(){
    asm volatile("cp.async.wait_group %0;\n" :: "n"(N));
}
__device__ __forceinline__ void ldsm4(unsigned &r0, unsigned &r1, unsigned &r2, unsigned &r3,
                                      const void* p){
    unsigned sa = (unsigned)__cvta_generic_to_shared(p);
    asm volatile("ldmatrix.sync.aligned.m8n8.x4.shared.b16 {%0,%1,%2,%3}, [%4];\n"
                 : "=r"(r0), "=r"(r1), "=r"(r2), "=r"(r3) : "r"(sa));
}
__device__ __forceinline__ unsigned short cvt2_e4m3(float hi, float lo){
    unsigned short r;
    asm("cvt.rn.satfinite.e4m3x2.f32 %0, %1, %2;" : "=h"(r) : "f"(hi), "f"(lo));
    return r;
}

// ---------------- union-find ----------------
__device__ __forceinline__ int uf_find(int* parent, int x){
    while (true){
        int p = parent[x];
        if (p == x) return x;
        int gp = parent[p];
        if (gp != p){ parent[x] = gp; x = gp; }
        else return p;
    }
}
__device__ __forceinline__ void uf_union(int* parent, int a, int b){
    while (true){
        a = uf_find(parent, a);
        b = uf_find(parent, b);
        if (a == b) return;
        if (a > b){ int t=a; a=b; b=t; }
        if (atomicCAS(&parent[b], b, a) == b) return;
    }
}

// ---------------- kInit: scores/sel/argmax-fallback/compaction ----------------
__global__ void kInit(const float* __restrict__ logits){
    int b = blockIdx.x, t = threadIdx.x;       // 1024 threads
    const int IPT = 6;
    int base = t*IPT;
    int sel[IPT];
    ull myMax = 0ULL; int myCnt = 0;
    #pragma unroll
    for (int i=0;i<IPT;i++){
        sel[i]=0;
        int n = base+i;
        if (n < Nq){
            int l = n/Qq, q = n%Qq;
            float lg = logits[(l*Bq+b)*Qq+q];
            float s = 1.f/(1.f+expf(-lg));
            sel[i] = (lg >= 0.f) ? 1 : 0;
            myCnt += sel[i];
            ull key = ((ull)__float_as_uint(s)<<32) | (ull)(0xFFFFFFFFu-(unsigned)n);
            if (key > myMax) myMax = key;
            int idx = b*Nq+n;
            g_score[idx] = s;
            g_parent[idx] = n;
            g_best[idx] = 0ULL;
        }
    }
    __shared__ int  redc[32];
    __shared__ ull  redm[32];
    __shared__ int  wsum[32];
    int lane = t & 31, wid = t >> 5;
    int c = myCnt; ull mx = myMax;
    #pragma unroll
    for (int o=16;o>0;o>>=1){
        c += __shfl_xor_sync(0xFFFFFFFFu, c, o);
        ull om = __shfl_xor_sync(0xFFFFFFFFu, mx, o);
        if (om > mx) mx = om;
    }
    if (lane == 0){ redc[wid]=c; redm[wid]=mx; }
    __syncthreads();
    if (wid == 0){
        c = redc[lane]; mx = redm[lane];
        #pragma unroll
        for (int o=16;o>0;o>>=1){
            c += __shfl_xor_sync(0xFFFFFFFFu, c, o);
            ull om = __shfl_xor_sync(0xFFFFFFFFu, mx, o);
            if (om > mx) mx = om;
        }
        if (lane == 0){ redc[0]=c; redm[0]=mx; }
    }
    __syncthreads();
    int cnt = redc[0]; ull bm = redm[0];
    if (cnt == 0){
        unsigned am = 0xFFFFFFFFu - (unsigned)(bm & 0xFFFFFFFFull);
        #pragma unroll
        for (int i=0;i<IPT;i++) sel[i] = ((unsigned)(base+i) == am) ? 1 : 0;
    }
    int s2 = 0;
    #pragma unroll
    for (int i=0;i<IPT;i++){
        int n = base+i;
        if (n < Nq) g_sel[b*Nq+n] = (unsigned char)sel[i];
        s2 += sel[i];
    }
    int v = s2;
    #pragma unroll
    for (int o=1;o<32;o<<=1){ int u=__shfl_up_sync(0xFFFFFFFFu,v,o); if(lane>=o) v+=u; }
    if (lane == 31) wsum[wid] = v;
    __syncthreads();
    if (wid == 0){
        int ww = wsum[lane];
        #pragma unroll
        for (int o=1;o<32;o<<=1){ int u=__shfl_up_sync(0xFFFFFFFFu,ww,o); if(lane>=o) ww+=u; }
        wsum[lane] = ww;
    }
    __syncthreads();
    int excl = v - s2 + (wid > 0 ? wsum[wid-1] : 0);
    if (t == 0) g_selCount[b] = wsum[31];
    int p = excl;
    #pragma unroll
    for (int i=0;i<IPT;i++){
        if (sel[i]){ g_selList[b*Nq + p] = base+i; p++; }
    }
}

// ---------------- k2: warp per selected row, normalize -> fp8 e4m3 ----------------
__global__ void k2_normalize(const float* __restrict__ qs){
    int w    = threadIdx.x >> 5;
    int lane = threadIdx.x & 31;
    int m    = blockIdx.x*8 + w;
    int b    = blockIdx.y;
    if (m >= g_selCount[b]) return;
    int n = g_selList[b*Nq + m];
    int l = n/Qq, q = n%Qq;
    const float4* src = (const float4*)(qs + (((size_t)l*Bq + b)*Qq + q)*Cq) + lane*2;
    float4 v0 = src[0], v1 = src[1];
    float s = v0.x*v0.x + v0.y*v0.y + v0.z*v0.z + v0.w*v0.w
            + v1.x*v1.x + v1.y*v1.y + v1.z*v1.z + v1.w*v1.w;
    #pragma unroll
    for (int o=16;o>0;o>>=1) s += __shfl_xor_sync(0xFFFFFFFFu, s, o);
    float r = rsqrtf(s + 1e-12f);
    // pack 8 fp8 bytes: byte i = element i  (cvt: first src -> upper byte)
    unsigned short p0 = cvt2_e4m3(v0.y*r, v0.x*r);
    unsigned short p1 = cvt2_e4m3(v0.w*r, v0.z*r);
    unsigned short p2 = cvt2_e4m3(v1.y*r, v1.x*r);
    unsigned short p3 = cvt2_e4m3(v1.w*r, v1.z*r);
    uint2 pk;
    pk.x = (unsigned)p0 | ((unsigned)p1 << 16);
    pk.y = (unsigned)p2 | ((unsigned)p3 << 16);
    *((uint2*)(g_normF8 + ((size_t)b*Nq + m)*Cq) + lane) = pk;
}

// ---------------- k3: fp8 e4m3 HMMA sim, fully unrolled 4-stage ----------------
__global__ void __launch_bounds__(256, 2) k3_sim(){
    int t  = blockIdx.x;
    int bx = (int)((sqrtf(8.0f*(float)t + 1.0f) - 1.0f) * 0.5f);
    while ((bx+1)*(bx+2)/2 <= t) bx++;
    while (bx*(bx+1)/2 > t) bx--;
    int by = t - bx*(bx+1)/2;
    int b  = blockIdx.z;
    int M  = g_selCount[b];
    int r0 = by*BM2, c0 = bx*BM2;
    if (c0 >= M) return;
    bool diag = (bx == by);

    extern __shared__ unsigned char sm[];
    unsigned char* Asb = sm;                       // [NSTG][BM2][ROWP]
    unsigned char* Bsb = sm + NSTG*BM2*ROWP;
    const unsigned char* Brd = diag ? Asb : Bsb;

    const unsigned char* base = g_normF8 + (size_t)b*Nq*Cq;
    int tid  = threadIdx.x;
    int lane = tid & 31;
    int w    = tid >> 5;
    int wm   = w >> 1, wn = w & 1;                 // 4x2 warps, warp tile 32x64
    int g    = lane >> 2;
    int tig  = lane & 3;

    auto load_stage = [&](int s, int k0){
        int nch = diag ? 512 : 1024;               // 16B chunks (A only on diagonal)
        for (int e = tid; e < nch; e += 256){
            int isB = e >> 9;
            int r   = (e & 511) >> 2;
            int ch  = e & 3;
            int gr  = isB ? (c0 + r) : (r0 + r);
            if (gr >= M) gr = 0;
            const void* gp = base + (size_t)gr*Cq + k0 + ch*16;
            unsigned char* dstb = isB ? Bsb : Asb;
            cp16(dstb + ((size_t)s*BM2 + r)*ROWP + ch*16, gp);
        }
        cp_commit();
    };

    float acc[2][8][4];
    #pragma unroll
    for (int i=0;i<2;i++)
        #pragma unroll
        for (int j=0;j<8;j++)
            #pragma unroll
            for (int c=0;c<4;c++) acc[i][j][c] = 0.f;

    load_stage(0, 0);
    load_stage(1, BKB);
    load_stage(2, 2*BKB);
    load_stage(3, 3*BKB);

    auto compute = [&](int s){
        #pragma unroll
        for (int ks=0; ks<2; ks++){
            int kk = ks*32;                        // 32 bytes per k32 step
            unsigned af[2][4];
            #pragma unroll
            for (int i=0;i<2;i++){
                int am = wm*32 + i*16;
                ldsm4(af[i][0], af[i][1], af[i][2], af[i][3],
                      Asb + ((size_t)s*BM2 + am + (lane & 15))*ROWP
                          + kk + ((lane >> 4) << 4));
            }
            unsigned bf[8][2];
            #pragma unroll
            for (int jj=0; jj<4; jj++){
                int bn = wn*64 + jj*16;
                ldsm4(bf[2*jj][0], bf[2*jj][1], bf[2*jj+1][0], bf[2*jj+1][1],
                      Brd + ((size_t)s*BM2 + bn + ((lane & 7) | ((lane >> 4) << 3)))*ROWP
                          + kk + (((lane >> 3) & 1) << 4));
            }
            #pragma unroll
            for (int i=0;i<2;i++)
                #pragma unroll
                for (int j=0;j<8;j++){
                    asm volatile(
                        "mma.sync.aligned.m16n8k32.row.col.f32.e4m3.e4m3.f32 "
                        "{%0,%1,%2,%3}, {%4,%5,%6,%7}, {%8,%9}, {%0,%1,%2,%3};"
                        : "+f"(acc[i][j][0]), "+f"(acc[i][j][1]),
                          "+f"(acc[i][j][2]), "+f"(acc[i][j][3])
                        : "r"(af[i][0]), "r"(af[i][1]), "r"(af[i][2]), "r"(af[i][3]),
                          "r"(bf[j][0]), "r"(bf[j][1]));
                }
        }
    };

    cp_wait<3>(); __syncthreads(); compute(0);
    cp_wait<2>(); __syncthreads(); compute(1);
    cp_wait<1>(); __syncthreads(); compute(2);
    cp_wait<0>(); __syncthreads(); compute(3);

    int* par = g_parent + b*Nq;
    const int* sl = g_selList + b*Nq;
    #pragma unroll
    for (int i=0;i<2;i++)
        #pragma unroll
        for (int j=0;j<8;j++)
            #pragma unroll
            for (int c=0;c<4;c++){
                int mi = r0 + wm*32 + i*16 + g + ((c>=2) ? 8 : 0);
                int mj = c0 + wn*64 + j*8 + 2*tig + (c & 1);
                if (mi < M && mj < M && acc[i][j][c] >= DUP_THR){
                    int ni = sl[mi], nj = sl[mj];
                    if (ni != nj) uf_union(par, ni, nj);
                }
            }
}

// ---------------- k4: parallel flatten + per-component best ----------------
__global__ void k4_flatten(){
    int idx = blockIdx.x*256 + threadIdx.x;
    if (idx >= Bq*Nq) return;
    int b = idx / Nq, n = idx % Nq;
    int* par = g_parent + b*Nq;
    int r = uf_find(par, n);
    par[n] = r;
    if (g_sel[idx]){
        ull key = ((ull)__float_as_uint(g_score[idx])<<32)
                | (ull)(0xFFFFFFFFu-(unsigned)n);
        atomicMax(&g_best[b*Nq + r], key);
    }
}

// ---------------- k5: per-image scan -> slotNode + seedCount ----------------
__global__ void k5_scan(){
    int b = blockIdx.x, t = threadIdx.x;           // 1024 threads
    const int IPT = 6;
    int base = t*IPT;
    int flags[IPT]; int s2 = 0;
    #pragma unroll
    for (int i=0;i<IPT;i++){
        int n = base+i; flags[i] = 0;
        if (n < Nq && g_sel[b*Nq+n] && g_parent[b*Nq+n] == n) flags[i] = 1;
        s2 += flags[i];
    }
    __shared__ int wsum[32];
    int lane = t & 31, wid = t >> 5;
    int v = s2;
    #pragma unroll
    for (int o=1;o<32;o<<=1){ int u=__shfl_up_sync(0xFFFFFFFFu,v,o); if(lane>=o) v+=u; }
    if (lane == 31) wsum[wid] = v;
    __syncthreads();
    if (wid == 0){
        int ww = wsum[lane];
        #pragma unroll
        for (int o=1;o<32;o<<=1){ int u=__shfl_up_sync(0xFFFFFFFFu,ww,o); if(lane>=o) ww+=u; }
        wsum[lane] = ww;
    }
    __syncthreads();
    int excl = v - s2 + (wid > 0 ? wsum[wid-1] : 0);
    if (t == 0) g_seedCount[b] = wsum[31];
    int p = excl;
    #pragma unroll
    for (int i=0;i<IPT;i++){
        if (flags[i]){
            int n = base+i;
            ull bk = g_best[b*Nq + n];
            int node = (int)(0xFFFFFFFFu - (unsigned)(bk & 0xFFFFFFFFull));
            g_slotNode[b*Nq + p] = node;
            p++;
        }
    }
}

// ---------------- k6: seed_signatures [B,N,C] + pad_mask + seed_scores ----------------
__global__ void k6_out(const float* __restrict__ qs, float* __restrict__ out){
    int w    = threadIdx.x >> 5;
    int lane = threadIdx.x & 31;
    int slot = blockIdx.x*8 + w;
    int b    = blockIdx.y;
    if (slot >= Nq) return;
    bool valid = (slot < g_seedCount[b]);
    int node = valid ? g_slotNode[b*Nq + slot] : 0;
    float4 o0 = make_float4(0,0,0,0), o1 = o0;
    if (valid){
        int l = node/Qq, q = node%Qq;
        const float4* src = (const float4*)(qs + (((size_t)l*Bq + b)*Qq + q)*Cq) + lane*2;
        o0 = src[0]; o1 = src[1];
    }
    float4* dst = (float4*)(out + ((size_t)b*Nq + slot)*Cq) + lane*2;
    dst[0] = o0; dst[1] = o1;
    if (lane == 0){
        float* maskOut  = out + (size_t)Bq*Nq*Cq;
        float* scoreOut = maskOut + Bq*Nq;
        maskOut[b*Nq + slot]  = valid ? 1.0f : 0.0f;
        scoreOut[b*Nq + slot] = valid ? g_score[b*Nq + node] : 0.0f;
    }
}

// ---------------- launch ----------------
extern "C" void kernel_launch(void* const* d_in, const int* in_sizes, int n_in,
                              void* d_out, int out_size){
    const float* qs     = (const float*)d_in[0];
    const float* logits = (const float*)d_in[1];
    float* out = (float*)d_out;
    (void)in_sizes; (void)n_in; (void)out_size;

    cudaFuncSetAttribute(k3_sim, cudaFuncAttributeMaxDynamicSharedMemorySize, DSMEM_BYTES);

    kInit<<<Bq, 1024>>>(logits);
    dim3 g2((Nq + 7)/8, Bq);
    k2_normalize<<<g2, 256>>>(qs);
    dim3 g3(TRI, 1, Bq);
    k3_sim<<<g3, 256, DSMEM_BYTES>>>();
    k4_flatten<<<(Bq*Nq + 255)/256, 256>>>();
    k5_scan<<<Bq, 1024>>>();
    k6_out<<<g2, 256>>>(qs, out);
}

// round 10
// speedup vs baseline: 1.0608x; 1.0608x over previous
#include <cuda_runtime.h>
#include <cuda_bf16.h>
#include <math.h>

#define Bq 4
#define Lq 6
#define Qq 900
#define Cq 256
#define Nq (Lq*Qq)            /* 5400 */
#define BMR 64                /* A rows per CTA */
#define BNC 128               /* B cols per CTA */
#define NTR ((Nq+BMR-1)/BMR)  /* 85 row tiles */
#define NTC ((Nq+BNC-1)/BNC)  /* 43 col tiles */
#define BKB 64                /* K bytes per stage (fp8) */
#define ROWP 80               /* padded smem row bytes */
#define NSTG 4
#define DUP_THR 0.8f
#define DSMEM_BYTES (NSTG*(BMR+BNC)*ROWP)   /* 61440 */

typedef unsigned long long ull;

// ---------------- scratch ----------------
__device__ unsigned char g_normF8[(size_t)Bq*Nq*Cq];   // fp8 e4m3 normalized rows
__device__ int           g_selList[Bq*Nq];
__device__ int           g_parent[Bq*Nq];
__device__ ull           g_best[Bq*Nq];
__device__ unsigned char g_sel[Bq*Nq];
__device__ float         g_score[Bq*Nq];
__device__ int           g_slotNode[Bq*Nq];
__device__ int           g_selCount[Bq];
__device__ int           g_seedCount[Bq];

// ---------------- ptx helpers ----------------
__device__ __forceinline__ void cp16(void* smp, const void* g){
    unsigned sa = (unsigned)__cvta_generic_to_shared(smp);
    asm volatile("cp.async.cg.shared.global [%0], [%1], 16;\n" :: "r"(sa), "l"(g));
}
__device__ __forceinline__ void cp_commit(){ asm volatile("cp.async.commit_group;\n"); }
template<int N> __device__ __forceinline__ void cp_wait(){
    asm volatile("cp.async.wait_group %0;\n" :: "n"(N));
}
__device__ __forceinline__ void ldsm4(unsigned &r0, unsigned &r1, unsigned &r2, unsigned &r3,
                                      const void* p){
    unsigned sa = (unsigned)__cvta_generic_to_shared(p);
    asm volatile("ldmatrix.sync.aligned.m8n8.x4.shared.b16 {%0,%1,%2,%3}, [%4];\n"
                 : "=r"(r0), "=r"(r1), "=r"(r2), "=r"(r3) : "r"(sa));
}
__device__ __forceinline__ unsigned short cvt2_e4m3(float hi, float lo){
    unsigned short r;
    asm("cvt.rn.satfinite.e4m3x2.f32 %0, %1, %2;" : "=h"(r) : "f"(hi), "f"(lo));
    return r;
}

// ---------------- union-find ----------------
__device__ __forceinline__ int uf_find(int* parent, int x){
    while (true){
        int p = parent[x];
        if (p == x) return x;
        int gp = parent[p];
        if (gp != p){ parent[x] = gp; x = gp; }
        else return p;
    }
}
__device__ __forceinline__ void uf_union(int* parent, int a, int b){
    while (true){
        a = uf_find(parent, a);
        b = uf_find(parent, b);
        if (a == b) return;
        if (a > b){ int t=a; a=b; b=t; }
        if (atomicCAS(&parent[b], b, a) == b) return;
    }
}

// ---------------- kInit: scores/sel/argmax-fallback/compaction ----------------
__global__ void kInit(const float* __restrict__ logits){
    int b = blockIdx.x, t = threadIdx.x;       // 1024 threads
    const int IPT = 6;
    int base = t*IPT;
    int sel[IPT];
    ull myMax = 0ULL; int myCnt = 0;
    #pragma unroll
    for (int i=0;i<IPT;i++){
        sel[i]=0;
        int n = base+i;
        if (n < Nq){
            int l = n/Qq, q = n%Qq;
            float lg = logits[(l*Bq+b)*Qq+q];
            float s = 1.f/(1.f+expf(-lg));
            sel[i] = (lg >= 0.f) ? 1 : 0;
            myCnt += sel[i];
            ull key = ((ull)__float_as_uint(s)<<32) | (ull)(0xFFFFFFFFu-(unsigned)n);
            if (key > myMax) myMax = key;
            int idx = b*Nq+n;
            g_score[idx] = s;
            g_parent[idx] = n;
            g_best[idx] = 0ULL;
        }
    }
    __shared__ int  redc[32];
    __shared__ ull  redm[32];
    __shared__ int  wsum[32];
    int lane = t & 31, wid = t >> 5;
    int c = myCnt; ull mx = myMax;
    #pragma unroll
    for (int o=16;o>0;o>>=1){
        c += __shfl_xor_sync(0xFFFFFFFFu, c, o);
        ull om = __shfl_xor_sync(0xFFFFFFFFu, mx, o);
        if (om > mx) mx = om;
    }
    if (lane == 0){ redc[wid]=c; redm[wid]=mx; }
    __syncthreads();
    if (wid == 0){
        c = redc[lane]; mx = redm[lane];
        #pragma unroll
        for (int o=16;o>0;o>>=1){
            c += __shfl_xor_sync(0xFFFFFFFFu, c, o);
            ull om = __shfl_xor_sync(0xFFFFFFFFu, mx, o);
            if (om > mx) mx = om;
        }
        if (lane == 0){ redc[0]=c; redm[0]=mx; }
    }
    __syncthreads();
    int cnt = redc[0]; ull bm = redm[0];
    if (cnt == 0){
        unsigned am = 0xFFFFFFFFu - (unsigned)(bm & 0xFFFFFFFFull);
        #pragma unroll
        for (int i=0;i<IPT;i++) sel[i] = ((unsigned)(base+i) == am) ? 1 : 0;
    }
    int s2 = 0;
    #pragma unroll
    for (int i=0;i<IPT;i++){
        int n = base+i;
        if (n < Nq) g_sel[b*Nq+n] = (unsigned char)sel[i];
        s2 += sel[i];
    }
    int v = s2;
    #pragma unroll
    for (int o=1;o<32;o<<=1){ int u=__shfl_up_sync(0xFFFFFFFFu,v,o); if(lane>=o) v+=u; }
    if (lane == 31) wsum[wid] = v;
    __syncthreads();
    if (wid == 0){
        int ww = wsum[lane];
        #pragma unroll
        for (int o=1;o<32;o<<=1){ int u=__shfl_up_sync(0xFFFFFFFFu,ww,o); if(lane>=o) ww+=u; }
        wsum[lane] = ww;
    }
    __syncthreads();
    int excl = v - s2 + (wid > 0 ? wsum[wid-1] : 0);
    if (t == 0) g_selCount[b] = wsum[31];
    int p = excl;
    #pragma unroll
    for (int i=0;i<IPT;i++){
        if (sel[i]){ g_selList[b*Nq + p] = base+i; p++; }
    }
}

// ---------------- k2: warp per selected row, normalize -> fp8 e4m3 ----------------
__global__ void k2_normalize(const float* __restrict__ qs){
    int w    = threadIdx.x >> 5;
    int lane = threadIdx.x & 31;
    int m    = blockIdx.x*8 + w;
    int b    = blockIdx.y;
    if (m >= g_selCount[b]) return;
    int n = g_selList[b*Nq + m];
    int l = n/Qq, q = n%Qq;
    const float4* src = (const float4*)(qs + (((size_t)l*Bq + b)*Qq + q)*Cq) + lane*2;
    float4 v0 = src[0], v1 = src[1];
    float s = v0.x*v0.x + v0.y*v0.y + v0.z*v0.z + v0.w*v0.w
            + v1.x*v1.x + v1.y*v1.y + v1.z*v1.z + v1.w*v1.w;
    #pragma unroll
    for (int o=16;o>0;o>>=1) s += __shfl_xor_sync(0xFFFFFFFFu, s, o);
    float r = rsqrtf(s + 1e-12f);
    unsigned short p0 = cvt2_e4m3(v0.y*r, v0.x*r);
    unsigned short p1 = cvt2_e4m3(v0.w*r, v0.z*r);
    unsigned short p2 = cvt2_e4m3(v1.y*r, v1.x*r);
    unsigned short p3 = cvt2_e4m3(v1.w*r, v1.z*r);
    uint2 pk;
    pk.x = (unsigned)p0 | ((unsigned)p1 << 16);
    pk.y = (unsigned)p2 | ((unsigned)p3 << 16);
    *((uint2*)(g_normF8 + ((size_t)b*Nq + m)*Cq) + lane) = pk;
}

// ---------------- k3: fp8 sim, 64x128 CTA tile, 3 CTA/SM ----------------
__global__ void __launch_bounds__(256, 3) k3_sim(){
    int b  = blockIdx.z;
    int M  = g_selCount[b];
    int r0 = blockIdx.y*BMR;         // A rows
    int c0 = blockIdx.x*BNC;         // B cols
    if (r0 >= M || c0 >= M) return;
    if (c0 + BNC - 1 < r0) return;   // below the needed upper-triangle band

    extern __shared__ unsigned char sm[];
    unsigned char* Asb = sm;                         // [NSTG][BMR][ROWP]
    unsigned char* Bsb = sm + NSTG*BMR*ROWP;         // [NSTG][BNC][ROWP]

    const unsigned char* base = g_normF8 + (size_t)b*Nq*Cq;
    int tid  = threadIdx.x;
    int lane = tid & 31;
    int w    = tid >> 5;
    int wm   = w >> 2, wn = w & 3;                   // 2x4 warps, warp tile 32x32
    int g    = lane >> 2;
    int tig  = lane & 3;

    auto load_stage = [&](int s, int k0){
        #pragma unroll
        for (int it=0; it<3; it++){
            int e = tid + it*256;                    // 0..767
            const void* gp;
            void* sp;
            if (e < 256){                            // A: 64 rows x 4 chunks
                int r = e >> 2, ch = e & 3;
                int gr = r0 + r; if (gr >= M) gr = 0;
                gp = base + (size_t)gr*Cq + k0 + ch*16;
                sp = Asb + ((size_t)s*BMR + r)*ROWP + ch*16;
            } else {                                 // B: 128 rows x 4 chunks
                int e2 = e - 256;
                int r = e2 >> 2, ch = e2 & 3;
                int gr = c0 + r; if (gr >= M) gr = 0;
                gp = base + (size_t)gr*Cq + k0 + ch*16;
                sp = Bsb + ((size_t)s*BNC + r)*ROWP + ch*16;
            }
            cp16(sp, gp);
        }
        cp_commit();
    };

    float acc[2][4][4];
    #pragma unroll
    for (int i=0;i<2;i++)
        #pragma unroll
        for (int j=0;j<4;j++)
            #pragma unroll
            for (int c=0;c<4;c++) acc[i][j][c] = 0.f;

    load_stage(0, 0);
    load_stage(1, BKB);
    load_stage(2, 2*BKB);
    load_stage(3, 3*BKB);

    auto compute = [&](int s){
        #pragma unroll
        for (int ks=0; ks<2; ks++){
            int kk = ks*32;
            unsigned af[2][4];
            #pragma unroll
            for (int i=0;i<2;i++){
                int am = wm*32 + i*16;
                ldsm4(af[i][0], af[i][1], af[i][2], af[i][3],
                      Asb + ((size_t)s*BMR + am + (lane & 15))*ROWP
                          + kk + ((lane >> 4) << 4));
            }
            unsigned bf[4][2];
            #pragma unroll
            for (int jj=0; jj<2; jj++){
                int bn = wn*32 + jj*16;
                ldsm4(bf[2*jj][0], bf[2*jj][1], bf[2*jj+1][0], bf[2*jj+1][1],
                      Bsb + ((size_t)s*BNC + bn + ((lane & 7) | ((lane >> 4) << 3)))*ROWP
                          + kk + (((lane >> 3) & 1) << 4));
            }
            #pragma unroll
            for (int i=0;i<2;i++)
                #pragma unroll
                for (int j=0;j<4;j++){
                    asm volatile(
                        "mma.sync.aligned.m16n8k32.row.col.f32.e4m3.e4m3.f32 "
                        "{%0,%1,%2,%3}, {%4,%5,%6,%7}, {%8,%9}, {%0,%1,%2,%3};"
                        : "+f"(acc[i][j][0]), "+f"(acc[i][j][1]),
                          "+f"(acc[i][j][2]), "+f"(acc[i][j][3])
                        : "r"(af[i][0]), "r"(af[i][1]), "r"(af[i][2]), "r"(af[i][3]),
                          "r"(bf[j][0]), "r"(bf[j][1]));
                }
        }
    };

    cp_wait<3>(); __syncthreads(); compute(0);
    cp_wait<2>(); __syncthreads(); compute(1);
    cp_wait<1>(); __syncthreads(); compute(2);
    cp_wait<0>(); __syncthreads(); compute(3);

    int* par = g_parent + b*Nq;
    const int* sl = g_selList + b*Nq;
    #pragma unroll
    for (int i=0;i<2;i++)
        #pragma unroll
        for (int j=0;j<4;j++)
            #pragma unroll
            for (int c=0;c<4;c++){
                int mi = r0 + wm*32 + i*16 + g + ((c>=2) ? 8 : 0);
                int mj = c0 + wn*32 + j*8 + 2*tig + (c & 1);
                if (mi < M && mj < M && acc[i][j][c] >= DUP_THR){
                    int ni = sl[mi], nj = sl[mj];
                    if (ni != nj) uf_union(par, ni, nj);
                }
            }
}

// ---------------- k4: parallel flatten + per-component best ----------------
__global__ void k4_flatten(){
    int idx = blockIdx.x*256 + threadIdx.x;
    if (idx >= Bq*Nq) return;
    int b = idx / Nq, n = idx % Nq;
    int* par = g_parent + b*Nq;
    int r = uf_find(par, n);
    par[n] = r;
    if (g_sel[idx]){
        ull key = ((ull)__float_as_uint(g_score[idx])<<32)
                | (ull)(0xFFFFFFFFu-(unsigned)n);
        atomicMax(&g_best[b*Nq + r], key);
    }
}

// ---------------- k5: per-image scan -> slotNode + seedCount ----------------
__global__ void k5_scan(){
    int b = blockIdx.x, t = threadIdx.x;           // 1024 threads
    const int IPT = 6;
    int base = t*IPT;
    int flags[IPT]; int s2 = 0;
    #pragma unroll
    for (int i=0;i<IPT;i++){
        int n = base+i; flags[i] = 0;
        if (n < Nq && g_sel[b*Nq+n] && g_parent[b*Nq+n] == n) flags[i] = 1;
        s2 += flags[i];
    }
    __shared__ int wsum[32];
    int lane = t & 31, wid = t >> 5;
    int v = s2;
    #pragma unroll
    for (int o=1;o<32;o<<=1){ int u=__shfl_up_sync(0xFFFFFFFFu,v,o); if(lane>=o) v+=u; }
    if (lane == 31) wsum[wid] = v;
    __syncthreads();
    if (wid == 0){
        int ww = wsum[lane];
        #pragma unroll
        for (int o=1;o<32;o<<=1){ int u=__shfl_up_sync(0xFFFFFFFFu,ww,o); if(lane>=o) ww+=u; }
        wsum[lane] = ww;
    }
    __syncthreads();
    int excl = v - s2 + (wid > 0 ? wsum[wid-1] : 0);
    if (t == 0) g_seedCount[b] = wsum[31];
    int p = excl;
    #pragma unroll
    for (int i=0;i<IPT;i++){
        if (flags[i]){
            int n = base+i;
            ull bk = g_best[b*Nq + n];
            int node = (int)(0xFFFFFFFFu - (unsigned)(bk & 0xFFFFFFFFull));
            g_slotNode[b*Nq + p] = node;
            p++;
        }
    }
}

// ---------------- k6: seed_signatures + pad_mask + seed_scores ----------------
__global__ void k6_out(const float* __restrict__ qs, float* __restrict__ out){
    int w    = threadIdx.x >> 5;
    int lane = threadIdx.x & 31;
    int slot = blockIdx.x*8 + w;
    int b    = blockIdx.y;
    if (slot >= Nq) return;
    bool valid = (slot < g_seedCount[b]);
    int node = valid ? g_slotNode[b*Nq + slot] : 0;
    float4 o0 = make_float4(0,0,0,0), o1 = o0;
    if (valid){
        int l = node/Qq, q = node%Qq;
        const float4* src = (const float4*)(qs + (((size_t)l*Bq + b)*Qq + q)*Cq) + lane*2;
        o0 = src[0]; o1 = src[1];
    }
    float4* dst = (float4*)(out + ((size_t)b*Nq + slot)*Cq) + lane*2;
    dst[0] = o0; dst[1] = o1;
    if (lane == 0){
        float* maskOut  = out + (size_t)Bq*Nq*Cq;
        float* scoreOut = maskOut + Bq*Nq;
        maskOut[b*Nq + slot]  = valid ? 1.0f : 0.0f;
        scoreOut[b*Nq + slot] = valid ? g_score[b*Nq + node] : 0.0f;
    }
}

// ---------------- launch ----------------
extern "C" void kernel_launch(void* const* d_in, const int* in_sizes, int n_in,
                              void* d_out, int out_size){
    const float* qs     = (const float*)d_in[0];
    const float* logits = (const float*)d_in[1];
    float* out = (float*)d_out;
    (void)in_sizes; (void)n_in; (void)out_size;

    cudaFuncSetAttribute(k3_sim, cudaFuncAttributeMaxDynamicSharedMemorySize, DSMEM_BYTES);

    kInit<<<Bq, 1024>>>(logits);
    dim3 g2((Nq + 7)/8, Bq);
    k2_normalize<<<g2, 256>>>(qs);
    dim3 g3(NTC, NTR, Bq);
    k3_sim<<<g3, 256, DSMEM_BYTES>>>();
    k4_flatten<<<(Bq*Nq + 255)/256, 256>>>();
    k5_scan<<<Bq, 1024>>>();
    k6_out<<<g2, 256>>>(qs, out);
}

// round 11
// speedup vs baseline: 1.0684x; 1.0071x over previous
#include <cuda_runtime.h>
#include <cuda_bf16.h>
#include <math.h>

#define Bq 4
#define Lq 6
#define Qq 900
#define Cq 256
#define Nq (Lq*Qq)            /* 5400 */
#define BMR 64                /* A rows per CTA */
#define BNC 128               /* B cols per CTA */
#define BAND 1408             /* band tiles per image: 462 + 22*43 */
#define BKB 64                /* K bytes per stage (fp8) */
#define ROWP 80               /* padded smem row bytes */
#define NSTG 4
#define DUP_THR 0.8f
#define DSMEM_BYTES (NSTG*(BMR+BNC)*ROWP)   /* 61440 */

typedef unsigned long long ull;

// ---------------- scratch ----------------
__device__ unsigned char g_normF8[(size_t)Bq*Nq*Cq];
__device__ int           g_selList[Bq*Nq];
__device__ int           g_parent[Bq*Nq];
__device__ ull           g_best[Bq*Nq];
__device__ unsigned char g_sel[Bq*Nq];
__device__ float         g_score[Bq*Nq];
__device__ int           g_slotNode[Bq*Nq];
__device__ int           g_selCount[Bq];
__device__ int           g_seedCount[Bq];
__device__ int           g_anyUnion;

// ---------------- ptx helpers ----------------
__device__ __forceinline__ void cp16(void* smp, const void* g){
    unsigned sa = (unsigned)__cvta_generic_to_shared(smp);
    asm volatile("cp.async.cg.shared.global [%0], [%1], 16;\n" :: "r"(sa), "l"(g));
}
__device__ __forceinline__ void cp_commit(){ asm volatile("cp.async.commit_group;\n"); }
template<int N> __device__ __forceinline__ void cp_wait(){
    asm volatile("cp.async.wait_group %0;\n" :: "n"(N));
}
__device__ __forceinline__ void ldsm4(unsigned &r0, unsigned &r1, unsigned &r2, unsigned &r3,
                                      const void* p){
    unsigned sa = (unsigned)__cvta_generic_to_shared(p);
    asm volatile("ldmatrix.sync.aligned.m8n8.x4.shared.b16 {%0,%1,%2,%3}, [%4];\n"
                 : "=r"(r0), "=r"(r1), "=r"(r2), "=r"(r3) : "r"(sa));
}
__device__ __forceinline__ unsigned short cvt2_e4m3(float hi, float lo){
    unsigned short r;
    asm("cvt.rn.satfinite.e4m3x2.f32 %0, %1, %2;" : "=h"(r) : "f"(hi), "f"(lo));
    return r;
}

// ---------------- union-find ----------------
__device__ __forceinline__ int uf_find(int* parent, int x){
    while (true){
        int p = parent[x];
        if (p == x) return x;
        int gp = parent[p];
        if (gp != p){ parent[x] = gp; x = gp; }
        else return p;
    }
}
__device__ __forceinline__ void uf_union(int* parent, int a, int b){
    g_anyUnion = 1;                            // duplicates exist -> slow path
    while (true){
        a = uf_find(parent, a);
        b = uf_find(parent, b);
        if (a == b) return;
        if (a > b){ int t=a; a=b; b=t; }
        if (atomicCAS(&parent[b], b, a) == b) return;
    }
}

// ---------------- kInit: scores/sel/argmax-fallback/compaction ----------------
__global__ void kInit(const float* __restrict__ logits){
    int b = blockIdx.x, t = threadIdx.x;       // 1024 threads
    if (b == 0 && t == 0) g_anyUnion = 0;
    const int IPT = 6;
    int base = t*IPT;
    int sel[IPT];
    ull myMax = 0ULL; int myCnt = 0;
    #pragma unroll
    for (int i=0;i<IPT;i++){
        sel[i]=0;
        int n = base+i;
        if (n < Nq){
            int l = n/Qq, q = n%Qq;
            float lg = logits[(l*Bq+b)*Qq+q];
            float s = 1.f/(1.f+expf(-lg));
            sel[i] = (lg >= 0.f) ? 1 : 0;
            myCnt += sel[i];
            ull key = ((ull)__float_as_uint(s)<<32) | (ull)(0xFFFFFFFFu-(unsigned)n);
            if (key > myMax) myMax = key;
            int idx = b*Nq+n;
            g_score[idx] = s;
            g_parent[idx] = n;
            g_best[idx] = 0ULL;
        }
    }
    __shared__ int  redc[32];
    __shared__ ull  redm[32];
    __shared__ int  wsum[32];
    int lane = t & 31, wid = t >> 5;
    int c = myCnt; ull mx = myMax;
    #pragma unroll
    for (int o=16;o>0;o>>=1){
        c += __shfl_xor_sync(0xFFFFFFFFu, c, o);
        ull om = __shfl_xor_sync(0xFFFFFFFFu, mx, o);
        if (om > mx) mx = om;
    }
    if (lane == 0){ redc[wid]=c; redm[wid]=mx; }
    __syncthreads();
    if (wid == 0){
        c = redc[lane]; mx = redm[lane];
        #pragma unroll
        for (int o=16;o>0;o>>=1){
            c += __shfl_xor_sync(0xFFFFFFFFu, c, o);
            ull om = __shfl_xor_sync(0xFFFFFFFFu, mx, o);
            if (om > mx) mx = om;
        }
        if (lane == 0){ redc[0]=c; redm[0]=mx; }
    }
    __syncthreads();
    int cnt = redc[0]; ull bm = redm[0];
    if (cnt == 0){
        unsigned am = 0xFFFFFFFFu - (unsigned)(bm & 0xFFFFFFFFull);
        #pragma unroll
        for (int i=0;i<IPT;i++) sel[i] = ((unsigned)(base+i) == am) ? 1 : 0;
    }
    int s2 = 0;
    #pragma unroll
    for (int i=0;i<IPT;i++){
        int n = base+i;
        if (n < Nq) g_sel[b*Nq+n] = (unsigned char)sel[i];
        s2 += sel[i];
    }
    int v = s2;
    #pragma unroll
    for (int o=1;o<32;o<<=1){ int u=__shfl_up_sync(0xFFFFFFFFu,v,o); if(lane>=o) v+=u; }
    if (lane == 31) wsum[wid] = v;
    __syncthreads();
    if (wid == 0){
        int ww = wsum[lane];
        #pragma unroll
        for (int o=1;o<32;o<<=1){ int u=__shfl_up_sync(0xFFFFFFFFu,ww,o); if(lane>=o) ww+=u; }
        wsum[lane] = ww;
    }
    __syncthreads();
    int excl = v - s2 + (wid > 0 ? wsum[wid-1] : 0);
    if (t == 0) g_selCount[b] = wsum[31];
    int p = excl;
    #pragma unroll
    for (int i=0;i<IPT;i++){
        if (sel[i]){ g_selList[b*Nq + p] = base+i; p++; }
    }
}

// ---------------- k2: warp per selected row, normalize -> fp8 e4m3 ----------------
__global__ void k2_normalize(const float* __restrict__ qs){
    int w    = threadIdx.x >> 5;
    int lane = threadIdx.x & 31;
    int m    = blockIdx.x*8 + w;
    int b    = blockIdx.y;
    if (m >= g_selCount[b]) return;
    int n = g_selList[b*Nq + m];
    int l = n/Qq, q = n%Qq;
    const float4* src = (const float4*)(qs + (((size_t)l*Bq + b)*Qq + q)*Cq) + lane*2;
    float4 v0 = src[0], v1 = src[1];
    float s = v0.x*v0.x + v0.y*v0.y + v0.z*v0.z + v0.w*v0.w
            + v1.x*v1.x + v1.y*v1.y + v1.z*v1.z + v1.w*v1.w;
    #pragma unroll
    for (int o=16;o>0;o>>=1) s += __shfl_xor_sync(0xFFFFFFFFu, s, o);
    float r = rsqrtf(s + 1e-12f);
    unsigned short p0 = cvt2_e4m3(v0.y*r, v0.x*r);
    unsigned short p1 = cvt2_e4m3(v0.w*r, v0.z*r);
    unsigned short p2 = cvt2_e4m3(v1.y*r, v1.x*r);
    unsigned short p3 = cvt2_e4m3(v1.w*r, v1.z*r);
    uint2 pk;
    pk.x = (unsigned)p0 | ((unsigned)p1 << 16);
    pk.y = (unsigned)p2 | ((unsigned)p3 << 16);
    *((uint2*)(g_normF8 + ((size_t)b*Nq + m)*Cq) + lane) = pk;
}

// ---------------- k3: fp8 sim, 64x128 tile, exact band grid ----------------
__global__ void __launch_bounds__(256, 3) k3_sim(){
    // decode band tile t -> (bx, by), by <= min(2bx+1, 42)
    int t = blockIdx.x;
    int bx, by;
    if (t < 462){
        bx = (int)((sqrtf(4.0f*(float)t + 1.0f) - 1.0f) * 0.5f);
        while ((bx+1)*(bx+2) <= t) bx++;
        while (bx*(bx+1) > t) bx--;
        by = t - bx*(bx+1);
    } else {
        int u = t - 462;
        bx = 21 + u/43;
        by = u - (u/43)*43;
    }
    int b  = blockIdx.z;
    int M  = g_selCount[b];
    int r0 = by*BMR;
    int c0 = bx*BNC;
    if (r0 >= M || c0 >= M) return;

    extern __shared__ unsigned char sm[];
    unsigned char* Asb = sm;                         // [NSTG][BMR][ROWP]
    unsigned char* Bsb = sm + NSTG*BMR*ROWP;         // [NSTG][BNC][ROWP]

    const unsigned char* base = g_normF8 + (size_t)b*Nq*Cq;
    int tid  = threadIdx.x;
    int lane = tid & 31;
    int w    = tid >> 5;
    int wm   = w >> 2, wn = w & 3;                   // 2x4 warps, warp tile 32x32
    int g    = lane >> 2;
    int tig  = lane & 3;

    auto load_stage = [&](int s, int k0){
        #pragma unroll
        for (int it=0; it<3; it++){
            int e = tid + it*256;                    // 0..767
            const void* gp;
            void* sp;
            if (e < 256){                            // A: 64 rows x 4 chunks
                int r = e >> 2, ch = e & 3;
                int gr = r0 + r; if (gr >= M) gr = 0;
                gp = base + (size_t)gr*Cq + k0 + ch*16;
                sp = Asb + ((size_t)s*BMR + r)*ROWP + ch*16;
            } else {                                 // B: 128 rows x 4 chunks
                int e2 = e - 256;
                int r = e2 >> 2, ch = e2 & 3;
                int gr = c0 + r; if (gr >= M) gr = 0;
                gp = base + (size_t)gr*Cq + k0 + ch*16;
                sp = Bsb + ((size_t)s*BNC + r)*ROWP + ch*16;
            }
            cp16(sp, gp);
        }
        cp_commit();
    };

    float acc[2][4][4];
    #pragma unroll
    for (int i=0;i<2;i++)
        #pragma unroll
        for (int j=0;j<4;j++)
            #pragma unroll
            for (int c=0;c<4;c++) acc[i][j][c] = 0.f;

    load_stage(0, 0);
    load_stage(1, BKB);
    load_stage(2, 2*BKB);
    load_stage(3, 3*BKB);

    auto compute = [&](int s){
        #pragma unroll
        for (int ks=0; ks<2; ks++){
            int kk = ks*32;
            unsigned af[2][4];
            #pragma unroll
            for (int i=0;i<2;i++){
                int am = wm*32 + i*16;
                ldsm4(af[i][0], af[i][1], af[i][2], af[i][3],
                      Asb + ((size_t)s*BMR + am + (lane & 15))*ROWP
                          + kk + ((lane >> 4) << 4));
            }
            unsigned bf[4][2];
            #pragma unroll
            for (int jj=0; jj<2; jj++){
                int bn = wn*32 + jj*16;
                ldsm4(bf[2*jj][0], bf[2*jj][1], bf[2*jj+1][0], bf[2*jj+1][1],
                      Bsb + ((size_t)s*BNC + bn + ((lane & 7) | ((lane >> 4) << 3)))*ROWP
                          + kk + (((lane >> 3) & 1) << 4));
            }
            #pragma unroll
            for (int i=0;i<2;i++)
                #pragma unroll
                for (int j=0;j<4;j++){
                    asm volatile(
                        "mma.sync.aligned.m16n8k32.row.col.f32.e4m3.e4m3.f32 "
                        "{%0,%1,%2,%3}, {%4,%5,%6,%7}, {%8,%9}, {%0,%1,%2,%3};"
                        : "+f"(acc[i][j][0]), "+f"(acc[i][j][1]),
                          "+f"(acc[i][j][2]), "+f"(acc[i][j][3])
                        : "r"(af[i][0]), "r"(af[i][1]), "r"(af[i][2]), "r"(af[i][3]),
                          "r"(bf[j][0]), "r"(bf[j][1]));
                }
        }
    };

    cp_wait<3>(); __syncthreads(); compute(0);
    cp_wait<2>(); __syncthreads(); compute(1);
    cp_wait<1>(); __syncthreads(); compute(2);
    cp_wait<0>(); __syncthreads(); compute(3);

    int* par = g_parent + b*Nq;
    const int* sl = g_selList + b*Nq;
    #pragma unroll
    for (int i=0;i<2;i++)
        #pragma unroll
        for (int j=0;j<4;j++)
            #pragma unroll
            for (int c=0;c<4;c++){
                int mi = r0 + wm*32 + i*16 + g + ((c>=2) ? 8 : 0);
                int mj = c0 + wn*32 + j*8 + 2*tig + (c & 1);
                if (mi < M && mj < M && acc[i][j][c] >= DUP_THR){
                    int ni = sl[mi], nj = sl[mj];
                    if (ni != nj) uf_union(par, ni, nj);
                }
            }
}

// ---------------- k5: seed compaction (fast path: no unions) ----------------
__global__ void k5_seed(){
    int b = blockIdx.x, t = threadIdx.x;           // 1024 threads
    if (g_anyUnion == 0){
        // no duplicates: every selected node is its own component & best.
        int Msel = g_selCount[b];
        if (t == 0) g_seedCount[b] = Msel;
        for (int m = t; m < Msel; m += 1024)
            g_slotNode[b*Nq + m] = g_selList[b*Nq + m];
        return;
    }
    // slow path: flatten + best + scan (proven logic from earlier rounds)
    const int IPT = 6;
    int base = t*IPT;
    int* par = g_parent + b*Nq;
    int flags[IPT]; int s2 = 0;
    #pragma unroll
    for (int i=0;i<IPT;i++){
        flags[i] = 0;
        int n = base+i;
        if (n < Nq){
            int r = uf_find(par, n);
            par[n] = r;
            if (g_sel[b*Nq+n]){
                ull key = ((ull)__float_as_uint(g_score[b*Nq+n])<<32)
                        | (ull)(0xFFFFFFFFu-(unsigned)n);
                atomicMax(&g_best[b*Nq + r], key);
                if (r == n) flags[i] = 1;
            }
        }
        s2 += flags[i];
    }
    __syncthreads();
    __shared__ int wsum[32];
    int lane = t & 31, wid = t >> 5;
    int v = s2;
    #pragma unroll
    for (int o=1;o<32;o<<=1){ int u=__shfl_up_sync(0xFFFFFFFFu,v,o); if(lane>=o) v+=u; }
    if (lane == 31) wsum[wid] = v;
    __syncthreads();
    if (wid == 0){
        int ww = wsum[lane];
        #pragma unroll
        for (int o=1;o<32;o<<=1){ int u=__shfl_up_sync(0xFFFFFFFFu,ww,o); if(lane>=o) ww+=u; }
        wsum[lane] = ww;
    }
    __syncthreads();
    int excl = v - s2 + (wid > 0 ? wsum[wid-1] : 0);
    if (t == 0) g_seedCount[b] = wsum[31];
    int p = excl;
    #pragma unroll
    for (int i=0;i<IPT;i++){
        if (flags[i]){
            int n = base+i;
            ull bk = g_best[b*Nq + n];
            int node = (int)(0xFFFFFFFFu - (unsigned)(bk & 0xFFFFFFFFull));
            g_slotNode[b*Nq + p] = node;
            p++;
        }
    }
}

// ---------------- k6: seed_signatures + pad_mask + seed_scores ----------------
__global__ void k6_out(const float* __restrict__ qs, float* __restrict__ out){
    int w    = threadIdx.x >> 5;
    int lane = threadIdx.x & 31;
    int slot = blockIdx.x*8 + w;
    int b    = blockIdx.y;
    if (slot >= Nq) return;
    bool valid = (slot < g_seedCount[b]);
    int node = valid ? g_slotNode[b*Nq + slot] : 0;
    float4 o0 = make_float4(0,0,0,0), o1 = o0;
    if (valid){
        int l = node/Qq, q = node%Qq;
        const float4* src = (const float4*)(qs + (((size_t)l*Bq + b)*Qq + q)*Cq) + lane*2;
        o0 = src[0]; o1 = src[1];
    }
    float4* dst = (float4*)(out + ((size_t)b*Nq + slot)*Cq) + lane*2;
    dst[0] = o0; dst[1] = o1;
    if (lane == 0){
        float* maskOut  = out + (size_t)Bq*Nq*Cq;
        float* scoreOut = maskOut + Bq*Nq;
        maskOut[b*Nq + slot]  = valid ? 1.0f : 0.0f;
        scoreOut[b*Nq + slot] = valid ? g_score[b*Nq + node] : 0.0f;
    }
}

// ---------------- launch ----------------
extern "C" void kernel_launch(void* const* d_in, const int* in_sizes, int n_in,
                              void* d_out, int out_size){
    const float* qs     = (const float*)d_in[0];
    const float* logits = (const float*)d_in[1];
    float* out = (float*)d_out;
    (void)in_sizes; (void)n_in; (void)out_size;

    cudaFuncSetAttribute(k3_sim, cudaFuncAttributeMaxDynamicSharedMemorySize, DSMEM_BYTES);

    kInit<<<Bq, 1024>>>(logits);
    dim3 g2((Nq + 7)/8, Bq);
    k2_normalize<<<g2, 256>>>(qs);
    dim3 g3(BAND, 1, Bq);
    k3_sim<<<g3, 256, DSMEM_BYTES>>>();
    k5_seed<<<Bq, 1024>>>();
    k6_out<<<g2, 256>>>(qs, out);
}